// round 15
// baseline (speedup 1.0000x reference)
#include <cuda_runtime.h>
#include <cuda_fp16.h>

// ---------------- problem constants ----------------
#define B_SZ     2
#define L_SEQ    1024
#define D_MODEL  1024
#define D_INNER  4096
#define N_STATE  16
#define DT_RANK  64
#define M_ROWS   (B_SZ * L_SEQ)          // 2048
#define XDBL_LD  128                     // padded x_dbl leading dim

// ---------------- scratch (device globals; no allocs allowed) ----------------
__device__ float g_xz   [(long)M_ROWS * 2 * D_INNER]; // 2048 x 8192  (xc | res)
__device__ float g_u    [(long)M_ROWS * D_INNER];     // 2048 x 4096 (fp32 for scan)
__device__ float g_xdbl [(long)M_ROWS * XDBL_LD];     // 2048 x 128 (cols 96..127 pad)
__device__ float g_delta[(long)M_ROWS * D_INNER];     // 2048 x 4096
__device__ float g_partx[8L * M_ROWS * XDBL_LD];      // split-K partials (xdbl)
__device__ float g_party[4L * M_ROWS * D_MODEL];      // split-K partials (out)
__device__ __half g_ap [(long)M_ROWS * D_INNER];      // u/y fp16
__device__ __half g_ap2[(long)M_ROWS * DT_RANK];      // delta-GEMM A (fp16)
__device__ __half g_wp [(long)(2 * D_INNER) * D_MODEL]; // W' (fp16, transposed)

// ---------------- helpers ----------------
__device__ __forceinline__ float siluf(float x) { return x / (1.0f + __expf(-x)); }
__device__ __forceinline__ float softplusf(float x) {
    return (x > 0.0f) ? (x + log1pf(expf(-x))) : log1pf(expf(x));
}
__device__ __forceinline__ unsigned smem_u32(const void* p) {
    unsigned a;
    asm("{ .reg .u64 t; cvta.to.shared.u64 t, %1; cvt.u32.u64 %0, t; }" : "=r"(a) : "l"(p));
    return a;
}
#define SWZ128(o) ((o) ^ (((o) >> 3) & 0x70))

__device__ __forceinline__ void ldsm4(unsigned* r, unsigned addr) {
    asm volatile("ldmatrix.sync.aligned.m8n8.x4.shared.b16 {%0,%1,%2,%3}, [%4];"
                 : "=r"(r[0]), "=r"(r[1]), "=r"(r[2]), "=r"(r[3]) : "r"(addr));
}
__device__ __forceinline__ void mma16816(float* c, const unsigned* a, const unsigned* b) {
    asm volatile("mma.sync.aligned.m16n8k16.row.col.f32.f16.f16.f32 "
                 "{%0,%1,%2,%3}, {%4,%5,%6,%7}, {%8,%9}, {%0,%1,%2,%3};"
                 : "+f"(c[0]), "+f"(c[1]), "+f"(c[2]), "+f"(c[3])
                 : "r"(a[0]), "r"(a[1]), "r"(a[2]), "r"(a[3]), "r"(b[0]), "r"(b[1]));
}
#define CP_ASYNC16(dst, src) \
    asm volatile("cp.async.cg.shared.global [%0], [%1], 16;" :: "r"(dst), "l"(src) : "memory")
#define CP_COMMIT() asm volatile("cp.async.commit_group;" ::: "memory")
#define CP_WAIT(n)  asm volatile("cp.async.wait_group %0;" :: "n"(n) : "memory")

// ---------------- prep kernels (fp16 quantize) ----------------
__global__ __launch_bounds__(256)
void prep_act(const float* __restrict__ A, int lda, int K,
              __half* __restrict__ Ap)
{
    long idx = (long)blockIdx.x * 256 + threadIdx.x;
    long m = idx / K;
    int  k = (int)(idx % K);
    Ap[m * K + k] = __float2half_rn(A[m * lda + k]);
}

// W[K,N] -> W'[N,K] fp16 (transposed via smem tile)
__global__ __launch_bounds__(256)
void prep_w(const float* __restrict__ W, int N, int K,
            __half* __restrict__ Wp)
{
    __shared__ float th[32][33];
    int bk = blockIdx.x * 32, bn = blockIdx.y * 32;
    int tx = threadIdx.x & 31, ty = threadIdx.x >> 5;
#pragma unroll
    for (int j = 0; j < 4; j++) {
        int k = bk + ty + j * 8;
        th[ty + j * 8][tx] = W[(long)k * N + bn + tx];
    }
    __syncthreads();
#pragma unroll
    for (int j = 0; j < 4; j++) {
        int n = bn + ty + j * 8;
        Wp[(long)n * K + bk + tx] = __float2half_rn(th[tx][ty + j * 8]);
    }
}

// zero rows 96..127 of Wx' (N padded to 128, K=4096)
__global__ __launch_bounds__(256)
void zero_wp_pad(__half* __restrict__ Wp)
{
    long i = (long)blockIdx.x * 256 + threadIdx.x;
    Wp[96L * D_INNER + i] = __float2half_rn(0.0f);
}

__global__ __launch_bounds__(256)
void reduce_parts(const float* __restrict__ parts, float* __restrict__ dst,
                  long n, int np)
{
    long i = ((long)blockIdx.x * 256 + threadIdx.x) * 4;
    if (i >= n) return;
    float4 s = *reinterpret_cast<const float4*>(parts + i);
    for (int p = 1; p < np; p++) {
        float4 v = *reinterpret_cast<const float4*>(parts + (long)p * n + i);
        s.x += v.x; s.y += v.y; s.z += v.z; s.w += v.w;
    }
    *reinterpret_cast<float4*>(dst + i) = s;
}

// ---------------- warp-MMA fp16 GEMM: C[M,N] = A[M,K] @ W'[N,K]^T ----------
// BM=128, BN=128, BK=64 fp16 (128B rows, SW128), 3-stage cp.async ring,
// one __syncthreads per K-tile, 2 CTAs/SM. 8 warps of 32x64.
// blockIdx.z = split-K slice (T tiles each). EPI: 0=none, 1=softplus.
#define STAGES 3
#define STG    32768u
#define GSMEM_TOTAL (STAGES * 32768)

template<int EPI>
__global__ __launch_bounds__(256, 2)
void gemm_mma(const __half* __restrict__ Ap, int lda,
              const __half* __restrict__ Bp, int ldb,
              float* __restrict__ C, int ldc, int T, long csplit)
{
    extern __shared__ __align__(1024) char smem[];
    const unsigned sb = smem_u32(smem);
    const int tid  = threadIdx.x;
    const int lane = tid & 31;
    const int wid  = tid >> 5;
    const int wm   = (wid & 3) * 32;   // warp row offset
    const int wn   = (wid >> 2) * 64;  // warp col offset
    const long bm  = (long)blockIdx.y * 128;
    const long bn  = (long)blockIdx.x * 128;

    Ap += (long)blockIdx.z * T * 64;
    Bp += (long)blockIdx.z * T * 64;
    C  += (long)blockIdx.z * csplit;

    const int ldr  = tid >> 3;
    const int ldc8 = (tid & 7) * 8;

    float acc[2][8][4];
#pragma unroll
    for (int i = 0; i < 2; i++)
#pragma unroll
        for (int j = 0; j < 8; j++)
#pragma unroll
            for (int r = 0; r < 4; r++) acc[i][j][r] = 0.0f;

    auto load_tile = [&](int t, int s) {
        const __half* Ab = Ap + bm * lda + (long)t * 64;
        const __half* Bb = Bp + bn * ldb + (long)t * 64;
        unsigned oa = sb + (unsigned)s * STG;
        unsigned ob = oa + 16384u;
#pragma unroll
        for (int i = 0; i < 4; i++) {
            int r = ldr + 32 * i;
            unsigned sw = SWZ128((unsigned)(r * 128 + ldc8 * 2));
            CP_ASYNC16(oa + sw, Ab + (long)r * lda + ldc8);
            CP_ASYNC16(ob + sw, Bb + (long)r * ldb + ldc8);
        }
        CP_COMMIT();
    };

#pragma unroll
    for (int s = 0; s < STAGES - 1; s++) {
        if (s < T) load_tile(s, s);
        else       CP_COMMIT();
    }

    const int lr = lane & 15;
    const int lh = (lane >> 4) * 16;

    int stage = 0;
    for (int t = 0; t < T; t++) {
        CP_WAIT(STAGES - 2);
        __syncthreads();
        {
            int tn = t + STAGES - 1;
            int sn = stage + STAGES - 1; if (sn >= STAGES) sn -= STAGES;
            if (tn < T) load_tile(tn, sn);
            else        CP_COMMIT();
        }
        const unsigned sA = sb + (unsigned)stage * STG;
        const unsigned sB = sA + 16384u;
#pragma unroll
        for (int ks = 0; ks < 4; ks++) {
            const int kb = ks * 32;
            unsigned af[2][4];
#pragma unroll
            for (int im = 0; im < 2; im++) {
                unsigned addr = sA + SWZ128((unsigned)((wm + im * 16 + lr) * 128 + kb + lh));
                ldsm4(af[im], addr);
            }
            unsigned bf[8][2];
#pragma unroll
            for (int jn = 0; jn < 4; jn++) {
                unsigned q[4];
                unsigned addr = sB + SWZ128((unsigned)((wn + jn * 16 + lr) * 128 + kb + lh));
                ldsm4(q, addr);
                bf[2 * jn][0]     = q[0];
                bf[2 * jn][1]     = q[2];
                bf[2 * jn + 1][0] = q[1];
                bf[2 * jn + 1][1] = q[3];
            }
#pragma unroll
            for (int im = 0; im < 2; im++)
#pragma unroll
                for (int j = 0; j < 8; j++)
                    mma16816(acc[im][j], af[im], bf[j]);
        }
        if (++stage == STAGES) stage = 0;
    }

    const int gid = lane >> 2;
    const int tig = lane & 3;
#pragma unroll
    for (int im = 0; im < 2; im++) {
        long m0 = bm + wm + im * 16 + gid;
#pragma unroll
        for (int j = 0; j < 8; j++) {
            long n0 = bn + wn + j * 8 + 2 * tig;
            float c0 = acc[im][j][0], c1 = acc[im][j][1];
            float c2 = acc[im][j][2], c3 = acc[im][j][3];
            if (EPI == 1) {
                c0 = softplusf(c0); c1 = softplusf(c1);
                c2 = softplusf(c2); c3 = softplusf(c3);
            }
            *reinterpret_cast<float2*>(C + m0 * ldc + n0)       = make_float2(c0, c1);
            *reinterpret_cast<float2*>(C + (m0 + 8) * ldc + n0) = make_float2(c2, c3);
        }
    }
}

// ---------------- depthwise causal conv(4) + bias + SiLU + u-fp16 ----------
__global__ __launch_bounds__(256)
void conv_silu_kernel(const float* __restrict__ Wconv,
                      const float* __restrict__ bconv)
{
    long idx = (long)blockIdx.x * 256 + threadIdx.x;   // over B * L/4 * D
    int d  = (int)(idx & (D_INNER - 1));
    int t4 = (int)((idx >> 12) & (L_SEQ / 4 - 1));
    int b  = (int)(idx >> 20);
    int t0 = t4 * 4;

    float w0 = Wconv[d * 4 + 0], w1 = Wconv[d * 4 + 1];
    float w2 = Wconv[d * 4 + 2], w3 = Wconv[d * 4 + 3];
    float bc = bconv[d];

    const long rowbase = (long)(b * L_SEQ) * (2 * D_INNER) + d;
    float v[7];
#pragma unroll
    for (int i = 0; i < 7; i++) {
        int tt = t0 - 3 + i;
        v[i] = (tt >= 0) ? g_xz[rowbase + (long)tt * (2 * D_INNER)] : 0.0f;
    }

    long m = (long)(b * L_SEQ + t0);
#pragma unroll
    for (int q = 0; q < 4; q++) {
        float acc = bc;
        acc = fmaf(v[q],     w0, acc);
        acc = fmaf(v[q + 1], w1, acc);
        acc = fmaf(v[q + 2], w2, acc);
        acc = fmaf(v[q + 3], w3, acc);
        float uu = siluf(acc);
        g_u[(m + q) * D_INNER + d] = uu;
        g_ap[(m + q) * D_INNER + d] = __float2half_rn(uu);
    }
}

// ---------------- selective scan + epilogue + y-fp16 -----------------------
// Per-t serial chains broken: yv -> 4 partial accumulators (depth 4 FMA),
// da -> rolling group-of-4 powers {p^1..p^4}*(p^4)^g (depth ~6 MUL).
__global__ __launch_bounds__(128)
void scan_kernel(const float* __restrict__ A_log,
                 const float* __restrict__ Dp)
{
    extern __shared__ __align__(16) float sBC[];   // [L_SEQ][32]
    const int b = blockIdx.x >> 5;
    const int d = ((blockIdx.x & 31) << 7) + threadIdx.x;
    const long base = (long)b * L_SEQ;

    for (int i = threadIdx.x * 4; i < L_SEQ * 32; i += 128 * 4) {
        int t = i >> 5, c = i & 31;
        *reinterpret_cast<float4*>(&sBC[i]) =
            *reinterpret_cast<const float4*>(&g_xdbl[(base + t) * XDBL_LD + DT_RANK + c]);
    }
    __syncthreads();

    float A[N_STATE];
#pragma unroll
    for (int n = 0; n < N_STATE; n++)
        A[n] = -__expf(A_log[d * N_STATE + n]);
    const float A1 = A[0];
    bool fast = true;
#pragma unroll
    for (int n = 1; n < N_STATE; n++)
        fast = fast && (fabsf(A[n] - (float)(n + 1) * A1) <= 1e-4f * fabsf(A[n]) + 1e-30f);

    const float Dd = Dp[d];
    float h[N_STATE];
#pragma unroll
    for (int n = 0; n < N_STATE; n++) h[n] = 0.0f;

    float pdt[4], pu[4], pr[4];
#pragma unroll
    for (int q = 0; q < 4; q++) {
        long row = base + q;
        pdt[q] = g_delta[row * D_INNER + d];
        pu[q]  = g_u[row * D_INNER + d];
        pr[q]  = g_xz[row * (2 * D_INNER) + D_INNER + d];
    }

    for (int t0 = 0; t0 < L_SEQ; t0 += 4) {
        float cdt[4], cu[4], cr[4];
#pragma unroll
        for (int q = 0; q < 4; q++) { cdt[q] = pdt[q]; cu[q] = pu[q]; cr[q] = pr[q]; }
        if (t0 + 4 < L_SEQ) {
#pragma unroll
            for (int q = 0; q < 4; q++) {
                long row = base + t0 + 4 + q;
                pdt[q] = g_delta[row * D_INNER + d];
                pu[q]  = g_u[row * D_INNER + d];
                pr[q]  = g_xz[row * (2 * D_INNER) + D_INNER + d];
            }
        }
#pragma unroll
        for (int q = 0; q < 4; q++) {
            const int t = t0 + q;
            const float* BC = &sBC[t * 32];
            const float dt = cdt[q], uu = cu[q], rr = cr[q];
            const float dtu = dt * uu;
            float yv0 = 0.0f, yv1 = 0.0f, yv2 = 0.0f, yv3 = 0.0f;
            if (fast) {
                // rolling group-of-4 powers of p = exp(dt*A1)
                const float p1 = __expf(dt * A1);
                const float p2 = p1 * p1;
                const float p4 = p2 * p2;
                float da0 = p1, da1 = p2, da2 = p2 * p1, da3 = p4;
#pragma unroll
                for (int g = 0; g < 4; g++) {
                    const int n = g * 4;
                    h[n]     = fmaf(da0, h[n],     dtu * BC[n]);
                    h[n + 1] = fmaf(da1, h[n + 1], dtu * BC[n + 1]);
                    h[n + 2] = fmaf(da2, h[n + 2], dtu * BC[n + 2]);
                    h[n + 3] = fmaf(da3, h[n + 3], dtu * BC[n + 3]);
                    yv0 = fmaf(h[n],     BC[N_STATE + n],     yv0);
                    yv1 = fmaf(h[n + 1], BC[N_STATE + n + 1], yv1);
                    yv2 = fmaf(h[n + 2], BC[N_STATE + n + 2], yv2);
                    yv3 = fmaf(h[n + 3], BC[N_STATE + n + 3], yv3);
                    if (g < 3) { da0 *= p4; da1 *= p4; da2 *= p4; da3 *= p4; }
                }
            } else {
#pragma unroll
                for (int n = 0; n < N_STATE; n++) {
                    float da = __expf(dt * A[n]);
                    h[n] = fmaf(da, h[n], dtu * BC[n]);
                    yv0 = fmaf(h[n], BC[N_STATE + n], yv0);
                }
            }
            float yv = (yv0 + yv1) + (yv2 + yv3);
            float yo = (yv + uu * Dd) * siluf(rr);
            g_ap[(base + t) * D_INNER + d] = __float2half_rn(yo);
        }
    }
}

// ---------------- launcher ----------------
extern "C" void kernel_launch(void* const* d_in, const int* in_sizes, int n_in,
                              void* d_out, int out_size)
{
    (void)in_sizes; (void)n_in; (void)out_size;
    const float* x     = (const float*)d_in[0];
    const float* Win   = (const float*)d_in[1];
    const float* Wconv = (const float*)d_in[2];
    const float* bconv = (const float*)d_in[3];
    const float* Wx    = (const float*)d_in[4];
    const float* Wdt   = (const float*)d_in[5];
    const float* A_log = (const float*)d_in[6];
    const float* D     = (const float*)d_in[7];
    const float* Wout  = (const float*)d_in[8];
    float* out = (float*)d_out;

    float *xz, *xdbl, *delta, *partx, *party;
    __half *ap, *ap2, *wp;
    cudaGetSymbolAddress((void**)&xz,    g_xz);
    cudaGetSymbolAddress((void**)&xdbl,  g_xdbl);
    cudaGetSymbolAddress((void**)&delta, g_delta);
    cudaGetSymbolAddress((void**)&partx, g_partx);
    cudaGetSymbolAddress((void**)&party, g_party);
    cudaGetSymbolAddress((void**)&ap,    g_ap);
    cudaGetSymbolAddress((void**)&ap2,   g_ap2);
    cudaGetSymbolAddress((void**)&wp,    g_wp);

    cudaFuncSetAttribute(gemm_mma<0>, cudaFuncAttributeMaxDynamicSharedMemorySize, GSMEM_TOTAL);
    cudaFuncSetAttribute(gemm_mma<1>, cudaFuncAttributeMaxDynamicSharedMemorySize, GSMEM_TOTAL);
    const int scan_smem = L_SEQ * 32 * sizeof(float);
    cudaFuncSetAttribute(scan_kernel, cudaFuncAttributeMaxDynamicSharedMemorySize, scan_smem);

    // ---- GEMM1: xz = x @ Win   (2048 x 8192, K=1024, T=16) ----
    prep_w<<<dim3(D_MODEL / 32, 2 * D_INNER / 32), 256>>>(Win, 2 * D_INNER, D_MODEL, wp);
    prep_act<<<(M_ROWS * D_MODEL) / 256, 256>>>(x, D_MODEL, D_MODEL, ap);
    gemm_mma<0><<<dim3(2 * D_INNER / 128, M_ROWS / 128, 1), 256, GSMEM_TOTAL>>>(
        ap, D_MODEL, wp, D_MODEL, xz, 2 * D_INNER, 16, 0);

    // ---- conv + SiLU -> u (fp32) + u (fp16, into ap) ----
    conv_silu_kernel<<<(B_SZ * (L_SEQ / 4) * D_INNER) / 256, 256>>>(Wconv, bconv);

    // ---- x_dbl = u @ Wx   (2048 x 128pad, K=4096; split-K x8, T=8) ----
    prep_w<<<dim3(D_INNER / 32, 96 / 32), 256>>>(Wx, 96, D_INNER, wp);
    zero_wp_pad<<<(32 * D_INNER) / 256, 256>>>(wp);
    gemm_mma<0><<<dim3(1, M_ROWS / 128, 8), 256, GSMEM_TOTAL>>>(
        ap, D_INNER, wp, D_INNER, partx, XDBL_LD, 8, (long)M_ROWS * XDBL_LD);
    reduce_parts<<<(M_ROWS * XDBL_LD) / 1024, 256>>>(partx, xdbl, (long)M_ROWS * XDBL_LD, 8);

    // ---- delta = softplus(x_dbl[:, :64] @ Wdt)  (2048 x 4096, K=64, T=1) ----
    prep_w<<<dim3(DT_RANK / 32, D_INNER / 32), 256>>>(Wdt, D_INNER, DT_RANK, wp);
    prep_act<<<(M_ROWS * DT_RANK) / 256, 256>>>(xdbl, XDBL_LD, DT_RANK, ap2);
    gemm_mma<1><<<dim3(D_INNER / 128, M_ROWS / 128, 1), 256, GSMEM_TOTAL>>>(
        ap2, DT_RANK, wp, DT_RANK, delta, D_INNER, 1, 0);

    // ---- selective scan + epilogue -> y (fp16, into ap) ----
    prep_w<<<dim3(D_INNER / 32, D_MODEL / 32), 256>>>(Wout, D_MODEL, D_INNER, wp);
    scan_kernel<<<64, 128, scan_smem>>>(A_log, D);

    // ---- out = y @ Wout   (2048 x 1024, K=4096; split-K x4, T=16) ----
    gemm_mma<0><<<dim3(D_MODEL / 128, M_ROWS / 128, 4), 256, GSMEM_TOTAL>>>(
        ap, D_INNER, wp, D_INNER, party, D_MODEL, 16, (long)M_ROWS * D_MODEL);
    reduce_parts<<<(M_ROWS * D_MODEL) / 1024, 256>>>(party, out, (long)M_ROWS * D_MODEL, 4);
}

// round 16
// speedup vs baseline: 1.0611x; 1.0611x over previous
#include <cuda_runtime.h>
#include <cuda_fp16.h>

// ---------------- problem constants ----------------
#define B_SZ     2
#define L_SEQ    1024
#define D_MODEL  1024
#define D_INNER  4096
#define N_STATE  16
#define DT_RANK  64
#define M_ROWS   (B_SZ * L_SEQ)          // 2048
#define XDBL_LD  128                     // padded x_dbl leading dim

// ---------------- scratch (device globals; no allocs allowed) ----------------
__device__ float g_xz   [(long)M_ROWS * 2 * D_INNER]; // 2048 x 8192  (xc | res)
__device__ float g_u    [(long)M_ROWS * D_INNER];     // 2048 x 4096 (fp32 for scan)
__device__ float g_xdbl [(long)M_ROWS * XDBL_LD];     // 2048 x 128 (cols 96..127 pad)
__device__ float g_delta[(long)M_ROWS * D_INNER];     // 2048 x 4096
__device__ float g_partx[8L * M_ROWS * XDBL_LD];      // split-K partials (xdbl)
__device__ float g_party[4L * M_ROWS * D_MODEL];      // split-K partials (out)
__device__ __half g_ap [(long)M_ROWS * D_INNER];      // u/y fp16
__device__ __half g_ap2[(long)M_ROWS * DT_RANK];      // delta-GEMM A (fp16)
__device__ __half g_wp [(long)(2 * D_INNER) * D_MODEL]; // W' (fp16, transposed)

// ---------------- helpers ----------------
__device__ __forceinline__ float siluf(float x) { return x / (1.0f + __expf(-x)); }
__device__ __forceinline__ float softplusf(float x) {
    return (x > 0.0f) ? (x + log1pf(expf(-x))) : log1pf(expf(x));
}
__device__ __forceinline__ unsigned smem_u32(const void* p) {
    unsigned a;
    asm("{ .reg .u64 t; cvta.to.shared.u64 t, %1; cvt.u32.u64 %0, t; }" : "=r"(a) : "l"(p));
    return a;
}
#define SWZ128(o) ((o) ^ (((o) >> 3) & 0x70))

__device__ __forceinline__ void ldsm4(unsigned* r, unsigned addr) {
    asm volatile("ldmatrix.sync.aligned.m8n8.x4.shared.b16 {%0,%1,%2,%3}, [%4];"
                 : "=r"(r[0]), "=r"(r[1]), "=r"(r[2]), "=r"(r[3]) : "r"(addr));
}
__device__ __forceinline__ void mma16816(float* c, const unsigned* a, const unsigned* b) {
    asm volatile("mma.sync.aligned.m16n8k16.row.col.f32.f16.f16.f32 "
                 "{%0,%1,%2,%3}, {%4,%5,%6,%7}, {%8,%9}, {%0,%1,%2,%3};"
                 : "+f"(c[0]), "+f"(c[1]), "+f"(c[2]), "+f"(c[3])
                 : "r"(a[0]), "r"(a[1]), "r"(a[2]), "r"(a[3]), "r"(b[0]), "r"(b[1]));
}
#define CP_ASYNC16(dst, src) \
    asm volatile("cp.async.cg.shared.global [%0], [%1], 16;" :: "r"(dst), "l"(src) : "memory")
#define CP_COMMIT() asm volatile("cp.async.commit_group;" ::: "memory")
#define CP_WAIT(n)  asm volatile("cp.async.wait_group %0;" :: "n"(n) : "memory")

// ---------------- prep kernels (fp16 quantize) ----------------
__global__ __launch_bounds__(256)
void prep_act(const float* __restrict__ A, int lda, int K,
              __half* __restrict__ Ap)
{
    long idx = (long)blockIdx.x * 256 + threadIdx.x;
    long m = idx / K;
    int  k = (int)(idx % K);
    Ap[m * K + k] = __float2half_rn(A[m * lda + k]);
}

// W[K,N] -> W'[N,K] fp16 (transposed via smem tile)
__global__ __launch_bounds__(256)
void prep_w(const float* __restrict__ W, int N, int K,
            __half* __restrict__ Wp)
{
    __shared__ float th[32][33];
    int bk = blockIdx.x * 32, bn = blockIdx.y * 32;
    int tx = threadIdx.x & 31, ty = threadIdx.x >> 5;
#pragma unroll
    for (int j = 0; j < 4; j++) {
        int k = bk + ty + j * 8;
        th[ty + j * 8][tx] = W[(long)k * N + bn + tx];
    }
    __syncthreads();
#pragma unroll
    for (int j = 0; j < 4; j++) {
        int n = bn + ty + j * 8;
        Wp[(long)n * K + bk + tx] = __float2half_rn(th[tx][ty + j * 8]);
    }
}

// zero rows 96..127 of Wx' (N padded to 128, K=4096)
__global__ __launch_bounds__(256)
void zero_wp_pad(__half* __restrict__ Wp)
{
    long i = (long)blockIdx.x * 256 + threadIdx.x;
    Wp[96L * D_INNER + i] = __float2half_rn(0.0f);
}

// plain split-K reduce (for out GEMM)
__global__ __launch_bounds__(256)
void reduce_parts(const float* __restrict__ parts, float* __restrict__ dst,
                  long n, int np)
{
    long i = ((long)blockIdx.x * 256 + threadIdx.x) * 4;
    if (i >= n) return;
    float4 s = *reinterpret_cast<const float4*>(parts + i);
    for (int p = 1; p < np; p++) {
        float4 v = *reinterpret_cast<const float4*>(parts + (long)p * n + i);
        s.x += v.x; s.y += v.y; s.z += v.z; s.w += v.w;
    }
    *reinterpret_cast<float4*>(dst + i) = s;
}

// split-K reduce for xdbl + fused fp16 emit of cols 0..63 into ap2
__global__ __launch_bounds__(256)
void reduce_xdbl(const float* __restrict__ parts, float* __restrict__ dst,
                 __half* __restrict__ ap2, long n, int np)
{
    long i = ((long)blockIdx.x * 256 + threadIdx.x) * 4;
    if (i >= n) return;
    float4 s = *reinterpret_cast<const float4*>(parts + i);
    for (int p = 1; p < np; p++) {
        float4 v = *reinterpret_cast<const float4*>(parts + (long)p * n + i);
        s.x += v.x; s.y += v.y; s.z += v.z; s.w += v.w;
    }
    *reinterpret_cast<float4*>(dst + i) = s;
    long m = i >> 7;            // row
    int  c = (int)(i & 127);    // col (multiple of 4)
    if (c < DT_RANK) {
        __half2* o = reinterpret_cast<__half2*>(ap2 + m * DT_RANK + c);
        o[0] = __floats2half2_rn(s.x, s.y);
        o[1] = __floats2half2_rn(s.z, s.w);
    }
}

// ---------------- warp-MMA fp16 GEMM: C[M,N] = A[M,K] @ W'[N,K]^T ----------
// BM=128, BN=128, BK=64 fp16 (128B rows, SW128), 3-stage cp.async ring,
// one __syncthreads per K-tile, 2 CTAs/SM. 8 warps of 32x64.
// blockIdx.z = split-K slice (T tiles each). EPI: 0=none, 1=softplus.
#define STAGES 3
#define STG    32768u
#define GSMEM_TOTAL (STAGES * 32768)

template<int EPI>
__global__ __launch_bounds__(256, 2)
void gemm_mma(const __half* __restrict__ Ap, int lda,
              const __half* __restrict__ Bp, int ldb,
              float* __restrict__ C, int ldc, int T, long csplit)
{
    extern __shared__ __align__(1024) char smem[];
    const unsigned sb = smem_u32(smem);
    const int tid  = threadIdx.x;
    const int lane = tid & 31;
    const int wid  = tid >> 5;
    const int wm   = (wid & 3) * 32;   // warp row offset
    const int wn   = (wid >> 2) * 64;  // warp col offset
    const long bm  = (long)blockIdx.y * 128;
    const long bn  = (long)blockIdx.x * 128;

    Ap += (long)blockIdx.z * T * 64;
    Bp += (long)blockIdx.z * T * 64;
    C  += (long)blockIdx.z * csplit;

    const int ldr  = tid >> 3;
    const int ldc8 = (tid & 7) * 8;

    float acc[2][8][4];
#pragma unroll
    for (int i = 0; i < 2; i++)
#pragma unroll
        for (int j = 0; j < 8; j++)
#pragma unroll
            for (int r = 0; r < 4; r++) acc[i][j][r] = 0.0f;

    auto load_tile = [&](int t, int s) {
        const __half* Ab = Ap + bm * lda + (long)t * 64;
        const __half* Bb = Bp + bn * ldb + (long)t * 64;
        unsigned oa = sb + (unsigned)s * STG;
        unsigned ob = oa + 16384u;
#pragma unroll
        for (int i = 0; i < 4; i++) {
            int r = ldr + 32 * i;
            unsigned sw = SWZ128((unsigned)(r * 128 + ldc8 * 2));
            CP_ASYNC16(oa + sw, Ab + (long)r * lda + ldc8);
            CP_ASYNC16(ob + sw, Bb + (long)r * ldb + ldc8);
        }
        CP_COMMIT();
    };

#pragma unroll
    for (int s = 0; s < STAGES - 1; s++) {
        if (s < T) load_tile(s, s);
        else       CP_COMMIT();
    }

    const int lr = lane & 15;
    const int lh = (lane >> 4) * 16;

    int stage = 0;
    for (int t = 0; t < T; t++) {
        CP_WAIT(STAGES - 2);
        __syncthreads();
        {
            int tn = t + STAGES - 1;
            int sn = stage + STAGES - 1; if (sn >= STAGES) sn -= STAGES;
            if (tn < T) load_tile(tn, sn);
            else        CP_COMMIT();
        }
        const unsigned sA = sb + (unsigned)stage * STG;
        const unsigned sB = sA + 16384u;
#pragma unroll
        for (int ks = 0; ks < 4; ks++) {
            const int kb = ks * 32;
            unsigned af[2][4];
#pragma unroll
            for (int im = 0; im < 2; im++) {
                unsigned addr = sA + SWZ128((unsigned)((wm + im * 16 + lr) * 128 + kb + lh));
                ldsm4(af[im], addr);
            }
            unsigned bf[8][2];
#pragma unroll
            for (int jn = 0; jn < 4; jn++) {
                unsigned q[4];
                unsigned addr = sB + SWZ128((unsigned)((wn + jn * 16 + lr) * 128 + kb + lh));
                ldsm4(q, addr);
                bf[2 * jn][0]     = q[0];
                bf[2 * jn][1]     = q[2];
                bf[2 * jn + 1][0] = q[1];
                bf[2 * jn + 1][1] = q[3];
            }
#pragma unroll
            for (int im = 0; im < 2; im++)
#pragma unroll
                for (int j = 0; j < 8; j++)
                    mma16816(acc[im][j], af[im], bf[j]);
        }
        if (++stage == STAGES) stage = 0;
    }

    const int gid = lane >> 2;
    const int tig = lane & 3;
#pragma unroll
    for (int im = 0; im < 2; im++) {
        long m0 = bm + wm + im * 16 + gid;
#pragma unroll
        for (int j = 0; j < 8; j++) {
            long n0 = bn + wn + j * 8 + 2 * tig;
            float c0 = acc[im][j][0], c1 = acc[im][j][1];
            float c2 = acc[im][j][2], c3 = acc[im][j][3];
            if (EPI == 1) {
                c0 = softplusf(c0); c1 = softplusf(c1);
                c2 = softplusf(c2); c3 = softplusf(c3);
            }
            *reinterpret_cast<float2*>(C + m0 * ldc + n0)       = make_float2(c0, c1);
            *reinterpret_cast<float2*>(C + (m0 + 8) * ldc + n0) = make_float2(c2, c3);
        }
    }
}

// ---------------- depthwise causal conv(4) + bias + SiLU + u-fp16 ----------
__global__ __launch_bounds__(256)
void conv_silu_kernel(const float* __restrict__ Wconv,
                      const float* __restrict__ bconv)
{
    long idx = (long)blockIdx.x * 256 + threadIdx.x;   // over B * L/4 * D
    int d  = (int)(idx & (D_INNER - 1));
    int t4 = (int)((idx >> 12) & (L_SEQ / 4 - 1));
    int b  = (int)(idx >> 20);
    int t0 = t4 * 4;

    float w0 = Wconv[d * 4 + 0], w1 = Wconv[d * 4 + 1];
    float w2 = Wconv[d * 4 + 2], w3 = Wconv[d * 4 + 3];
    float bc = bconv[d];

    const long rowbase = (long)(b * L_SEQ) * (2 * D_INNER) + d;
    float v[7];
#pragma unroll
    for (int i = 0; i < 7; i++) {
        int tt = t0 - 3 + i;
        v[i] = (tt >= 0) ? g_xz[rowbase + (long)tt * (2 * D_INNER)] : 0.0f;
    }

    long m = (long)(b * L_SEQ + t0);
#pragma unroll
    for (int q = 0; q < 4; q++) {
        float acc = bc;
        acc = fmaf(v[q],     w0, acc);
        acc = fmaf(v[q + 1], w1, acc);
        acc = fmaf(v[q + 2], w2, acc);
        acc = fmaf(v[q + 3], w3, acc);
        float uu = siluf(acc);
        g_u[(m + q) * D_INNER + d] = uu;
        g_ap[(m + q) * D_INNER + d] = __float2half_rn(uu);
    }
}

// ---------------- selective scan + epilogue + y-fp16 -----------------------
// (inner loop frozen at R14 form — measured optimum)
__global__ __launch_bounds__(128)
void scan_kernel(const float* __restrict__ A_log,
                 const float* __restrict__ Dp)
{
    extern __shared__ __align__(16) float sBC[];   // [L_SEQ][32]
    const int b = blockIdx.x >> 5;
    const int d = ((blockIdx.x & 31) << 7) + threadIdx.x;
    const long base = (long)b * L_SEQ;

    for (int i = threadIdx.x * 4; i < L_SEQ * 32; i += 128 * 4) {
        int t = i >> 5, c = i & 31;
        *reinterpret_cast<float4*>(&sBC[i]) =
            *reinterpret_cast<const float4*>(&g_xdbl[(base + t) * XDBL_LD + DT_RANK + c]);
    }
    __syncthreads();

    float A[N_STATE];
#pragma unroll
    for (int n = 0; n < N_STATE; n++)
        A[n] = -__expf(A_log[d * N_STATE + n]);
    const float A1 = A[0];
    bool fast = true;
#pragma unroll
    for (int n = 1; n < N_STATE; n++)
        fast = fast && (fabsf(A[n] - (float)(n + 1) * A1) <= 1e-4f * fabsf(A[n]) + 1e-30f);

    const float Dd = Dp[d];
    float h[N_STATE];
#pragma unroll
    for (int n = 0; n < N_STATE; n++) h[n] = 0.0f;

    float pdt[4], pu[4], pr[4];
#pragma unroll
    for (int q = 0; q < 4; q++) {
        long row = base + q;
        pdt[q] = g_delta[row * D_INNER + d];
        pu[q]  = g_u[row * D_INNER + d];
        pr[q]  = g_xz[row * (2 * D_INNER) + D_INNER + d];
    }

    for (int t0 = 0; t0 < L_SEQ; t0 += 4) {
        float cdt[4], cu[4], cr[4];
#pragma unroll
        for (int q = 0; q < 4; q++) { cdt[q] = pdt[q]; cu[q] = pu[q]; cr[q] = pr[q]; }
        if (t0 + 4 < L_SEQ) {
#pragma unroll
            for (int q = 0; q < 4; q++) {
                long row = base + t0 + 4 + q;
                pdt[q] = g_delta[row * D_INNER + d];
                pu[q]  = g_u[row * D_INNER + d];
                pr[q]  = g_xz[row * (2 * D_INNER) + D_INNER + d];
            }
        }
#pragma unroll
        for (int q = 0; q < 4; q++) {
            const int t = t0 + q;
            const float* BC = &sBC[t * 32];
            const float dt = cdt[q], uu = cu[q], rr = cr[q];
            const float dtu = dt * uu;
            float yv = 0.0f;
            if (fast) {
                const float p = __expf(dt * A1);
                float da = p;
#pragma unroll
                for (int n = 0; n < N_STATE; n++) {
                    h[n] = fmaf(da, h[n], dtu * BC[n]);
                    yv = fmaf(h[n], BC[N_STATE + n], yv);
                    da *= p;
                }
            } else {
#pragma unroll
                for (int n = 0; n < N_STATE; n++) {
                    float da = __expf(dt * A[n]);
                    h[n] = fmaf(da, h[n], dtu * BC[n]);
                    yv = fmaf(h[n], BC[N_STATE + n], yv);
                }
            }
            float yo = (yv + uu * Dd) * siluf(rr);
            g_ap[(base + t) * D_INNER + d] = __float2half_rn(yo);
        }
    }
}

// ---------------- launcher ----------------
extern "C" void kernel_launch(void* const* d_in, const int* in_sizes, int n_in,
                              void* d_out, int out_size)
{
    (void)in_sizes; (void)n_in; (void)out_size;
    const float* x     = (const float*)d_in[0];
    const float* Win   = (const float*)d_in[1];
    const float* Wconv = (const float*)d_in[2];
    const float* bconv = (const float*)d_in[3];
    const float* Wx    = (const float*)d_in[4];
    const float* Wdt   = (const float*)d_in[5];
    const float* A_log = (const float*)d_in[6];
    const float* D     = (const float*)d_in[7];
    const float* Wout  = (const float*)d_in[8];
    float* out = (float*)d_out;

    float *xz, *xdbl, *delta, *partx, *party;
    __half *ap, *ap2, *wp;
    cudaGetSymbolAddress((void**)&xz,    g_xz);
    cudaGetSymbolAddress((void**)&xdbl,  g_xdbl);
    cudaGetSymbolAddress((void**)&delta, g_delta);
    cudaGetSymbolAddress((void**)&partx, g_partx);
    cudaGetSymbolAddress((void**)&party, g_party);
    cudaGetSymbolAddress((void**)&ap,    g_ap);
    cudaGetSymbolAddress((void**)&ap2,   g_ap2);
    cudaGetSymbolAddress((void**)&wp,    g_wp);

    cudaFuncSetAttribute(gemm_mma<0>, cudaFuncAttributeMaxDynamicSharedMemorySize, GSMEM_TOTAL);
    cudaFuncSetAttribute(gemm_mma<1>, cudaFuncAttributeMaxDynamicSharedMemorySize, GSMEM_TOTAL);
    const int scan_smem = L_SEQ * 32 * sizeof(float);
    cudaFuncSetAttribute(scan_kernel, cudaFuncAttributeMaxDynamicSharedMemorySize, scan_smem);

    // ---- GEMM1: xz = x @ Win   (2048 x 8192, K=1024, T=16) ----
    prep_w<<<dim3(D_MODEL / 32, 2 * D_INNER / 32), 256>>>(Win, 2 * D_INNER, D_MODEL, wp);
    prep_act<<<(M_ROWS * D_MODEL) / 256, 256>>>(x, D_MODEL, D_MODEL, ap);
    gemm_mma<0><<<dim3(2 * D_INNER / 128, M_ROWS / 128, 1), 256, GSMEM_TOTAL>>>(
        ap, D_MODEL, wp, D_MODEL, xz, 2 * D_INNER, 16, 0);

    // ---- conv + SiLU -> u (fp32) + u (fp16, into ap) ----
    conv_silu_kernel<<<(B_SZ * (L_SEQ / 4) * D_INNER) / 256, 256>>>(Wconv, bconv);

    // ---- x_dbl = u @ Wx   (2048 x 128pad, K=4096; split-K x8, T=8) ----
    prep_w<<<dim3(D_INNER / 32, 96 / 32), 256>>>(Wx, 96, D_INNER, wp);
    zero_wp_pad<<<(32 * D_INNER) / 256, 256>>>(wp);
    gemm_mma<0><<<dim3(1, M_ROWS / 128, 8), 256, GSMEM_TOTAL>>>(
        ap, D_INNER, wp, D_INNER, partx, XDBL_LD, 8, (long)M_ROWS * XDBL_LD);
    // fused: reduce + fp16 emit of delta-GEMM input (cols 0..63)
    reduce_xdbl<<<(M_ROWS * XDBL_LD) / 1024, 256>>>(partx, xdbl, ap2,
                                                    (long)M_ROWS * XDBL_LD, 8);

    // ---- delta = softplus(x_dbl[:, :64] @ Wdt)  (2048 x 4096, K=64, T=1) ----
    prep_w<<<dim3(DT_RANK / 32, D_INNER / 32), 256>>>(Wdt, D_INNER, DT_RANK, wp);
    gemm_mma<1><<<dim3(D_INNER / 128, M_ROWS / 128, 1), 256, GSMEM_TOTAL>>>(
        ap2, DT_RANK, wp, DT_RANK, delta, D_INNER, 1, 0);

    // ---- selective scan + epilogue -> y (fp16, into ap) ----
    prep_w<<<dim3(D_INNER / 32, D_MODEL / 32), 256>>>(Wout, D_MODEL, D_INNER, wp);
    scan_kernel<<<64, 128, scan_smem>>>(A_log, D);

    // ---- out = y @ Wout   (2048 x 1024, K=4096; split-K x4, T=16) ----
    gemm_mma<0><<<dim3(D_MODEL / 128, M_ROWS / 128, 4), 256, GSMEM_TOTAL>>>(
        ap, D_INNER, wp, D_INNER, party, D_MODEL, 16, (long)M_ROWS * D_MODEL);
    reduce_parts<<<(M_ROWS * D_MODEL) / 1024, 256>>>(party, out, (long)M_ROWS * D_MODEL, 4);
}

// round 17
// speedup vs baseline: 1.0961x; 1.0329x over previous
#include <cuda_runtime.h>
#include <cuda_fp16.h>

// ---------------- problem constants ----------------
#define B_SZ     2
#define L_SEQ    1024
#define D_MODEL  1024
#define D_INNER  4096
#define N_STATE  16
#define DT_RANK  64
#define M_ROWS   (B_SZ * L_SEQ)          // 2048
#define XDBL_LD  128                     // padded x_dbl leading dim

// ---------------- scratch (device globals; no allocs allowed) ----------------
__device__ float g_xz   [(long)M_ROWS * 2 * D_INNER]; // 2048 x 8192  (xc | res)
__device__ float g_u    [(long)M_ROWS * D_INNER];     // 2048 x 4096 (fp32 for scan)
__device__ float g_xdbl [(long)M_ROWS * XDBL_LD];     // 2048 x 128 (cols 96..127 pad)
__device__ float g_delta[(long)M_ROWS * D_INNER];     // 2048 x 4096
__device__ float g_partx[8L * M_ROWS * XDBL_LD];      // split-K partials (xdbl)
__device__ float g_party[4L * M_ROWS * D_MODEL];      // split-K partials (out)
__device__ __half g_ap [(long)M_ROWS * D_INNER];      // u/y fp16 (also x' for GEMM1: 2048x1024 fits)
__device__ __half g_ax [(long)M_ROWS * D_MODEL];      // x fp16 (GEMM1 A)
__device__ __half g_ap2[(long)M_ROWS * DT_RANK];      // delta-GEMM A (fp16)
// per-weight fp16 buffers (transposed [N,K])
__device__ __half g_wpA[(long)(2 * D_INNER) * D_MODEL];  // Win'  8192x1024
__device__ __half g_wpB[(long)XDBL_LD * D_INNER];        // Wx'   128x4096 (pad rows zeroed)
__device__ __half g_wpC[(long)D_INNER * DT_RANK];        // Wdt'  4096x64
__device__ __half g_wpD[(long)D_MODEL * D_INNER];        // Wout' 1024x4096

// ---------------- helpers ----------------
__device__ __forceinline__ float siluf(float x) { return x / (1.0f + __expf(-x)); }
__device__ __forceinline__ float softplusf(float x) {
    return (x > 0.0f) ? (x + log1pf(expf(-x))) : log1pf(expf(x));
}
__device__ __forceinline__ unsigned smem_u32(const void* p) {
    unsigned a;
    asm("{ .reg .u64 t; cvta.to.shared.u64 t, %1; cvt.u32.u64 %0, t; }" : "=r"(a) : "l"(p));
    return a;
}
#define SWZ128(o) ((o) ^ (((o) >> 3) & 0x70))

__device__ __forceinline__ void ldsm4(unsigned* r, unsigned addr) {
    asm volatile("ldmatrix.sync.aligned.m8n8.x4.shared.b16 {%0,%1,%2,%3}, [%4];"
                 : "=r"(r[0]), "=r"(r[1]), "=r"(r[2]), "=r"(r[3]) : "r"(addr));
}
__device__ __forceinline__ void mma16816(float* c, const unsigned* a, const unsigned* b) {
    asm volatile("mma.sync.aligned.m16n8k16.row.col.f32.f16.f16.f32 "
                 "{%0,%1,%2,%3}, {%4,%5,%6,%7}, {%8,%9}, {%0,%1,%2,%3};"
                 : "+f"(c[0]), "+f"(c[1]), "+f"(c[2]), "+f"(c[3])
                 : "r"(a[0]), "r"(a[1]), "r"(a[2]), "r"(a[3]), "r"(b[0]), "r"(b[1]));
}
#define CP_ASYNC16(dst, src) \
    asm volatile("cp.async.cg.shared.global [%0], [%1], 16;" :: "r"(dst), "l"(src) : "memory")
#define CP_COMMIT() asm volatile("cp.async.commit_group;" ::: "memory")
#define CP_WAIT(n)  asm volatile("cp.async.wait_group %0;" :: "n"(n) : "memory")

// ---------------- fused prep: all weight transposes + x quantize -----------
// Section dispatch by linear block index. Each prep_w-style section uses
// 32x32 tiles via smem transpose. Wx section pads N to 128 with zeros.
__device__ __forceinline__ void prep_w_tile(const float* __restrict__ W,
                                            int N, int K, int Nfull,
                                            __half* __restrict__ Wp,
                                            int bk, int bn, int tid)
{
    __shared__ float th[32][33];
    int tx = tid & 31, ty = tid >> 5;
#pragma unroll
    for (int j = 0; j < 4; j++) {
        int k = bk + ty + j * 8;
        int n = bn + tx;
        th[ty + j * 8][tx] = (n < N) ? W[(long)k * N + n] : 0.0f;
    }
    __syncthreads();
#pragma unroll
    for (int j = 0; j < 4; j++) {
        int n = bn + ty + j * 8;
        Wp[(long)n * K + bk + tx] = __float2half_rn(th[tx][ty + j * 8]);
    }
}

#define SEC_A 8192            // Win:  (1024/32)x(8192/32) = 32x256
#define SEC_B 512             // Wx:   (4096/32)x(128/32)  = 128x4
#define SEC_C 256             // Wdt:  (64/32)x(4096/32)   = 2x128
#define SEC_D 4096            // Wout: (4096/32)x(1024/32) = 128x32
#define SEC_E 8192            // x quantize: 2048*1024/256
#define PREP_BLOCKS (SEC_A + SEC_B + SEC_C + SEC_D + SEC_E)

__global__ __launch_bounds__(256)
void prep_all(const float* __restrict__ x,
              const float* __restrict__ Win,
              const float* __restrict__ Wx,
              const float* __restrict__ Wdt,
              const float* __restrict__ Wout)
{
    int bid = blockIdx.x;
    int tid = threadIdx.x;
    if (bid < SEC_A) {
        int KB = D_MODEL / 32;   // 32
        prep_w_tile(Win, 2 * D_INNER, D_MODEL, 2 * D_INNER, g_wpA,
                    (bid % KB) * 32, (bid / KB) * 32, tid);
        return;
    }
    bid -= SEC_A;
    if (bid < SEC_B) {
        int KB = D_INNER / 32;   // 128
        prep_w_tile(Wx, 96, D_INNER, XDBL_LD, g_wpB,
                    (bid % KB) * 32, (bid / KB) * 32, tid);
        return;
    }
    bid -= SEC_B;
    if (bid < SEC_C) {
        int KB = DT_RANK / 32;   // 2
        prep_w_tile(Wdt, D_INNER, DT_RANK, D_INNER, g_wpC,
                    (bid % KB) * 32, (bid / KB) * 32, tid);
        return;
    }
    bid -= SEC_C;
    if (bid < SEC_D) {
        int KB = D_INNER / 32;   // 128
        prep_w_tile(Wout, D_MODEL, D_INNER, D_MODEL, g_wpD,
                    (bid % KB) * 32, (bid / KB) * 32, tid);
        return;
    }
    bid -= SEC_D;
    {   // x quantize: 2048 x 1024 contiguous
        long i = (long)bid * 256 + tid;
        g_ax[i] = __float2half_rn(x[i]);
    }
}

// plain split-K reduce (for out GEMM)
__global__ __launch_bounds__(256)
void reduce_parts(const float* __restrict__ parts, float* __restrict__ dst,
                  long n, int np)
{
    long i = ((long)blockIdx.x * 256 + threadIdx.x) * 4;
    if (i >= n) return;
    float4 s = *reinterpret_cast<const float4*>(parts + i);
    for (int p = 1; p < np; p++) {
        float4 v = *reinterpret_cast<const float4*>(parts + (long)p * n + i);
        s.x += v.x; s.y += v.y; s.z += v.z; s.w += v.w;
    }
    *reinterpret_cast<float4*>(dst + i) = s;
}

// split-K reduce for xdbl + fused fp16 emit of cols 0..63 into ap2
__global__ __launch_bounds__(256)
void reduce_xdbl(const float* __restrict__ parts, float* __restrict__ dst,
                 __half* __restrict__ ap2, long n, int np)
{
    long i = ((long)blockIdx.x * 256 + threadIdx.x) * 4;
    if (i >= n) return;
    float4 s = *reinterpret_cast<const float4*>(parts + i);
    for (int p = 1; p < np; p++) {
        float4 v = *reinterpret_cast<const float4*>(parts + (long)p * n + i);
        s.x += v.x; s.y += v.y; s.z += v.z; s.w += v.w;
    }
    *reinterpret_cast<float4*>(dst + i) = s;
    long m = i >> 7;            // row
    int  c = (int)(i & 127);    // col (multiple of 4)
    if (c < DT_RANK) {
        __half2* o = reinterpret_cast<__half2*>(ap2 + m * DT_RANK + c);
        o[0] = __floats2half2_rn(s.x, s.y);
        o[1] = __floats2half2_rn(s.z, s.w);
    }
}

// ---------------- warp-MMA fp16 GEMM: C[M,N] = A[M,K] @ W'[N,K]^T ----------
// BM=128, BN=128, BK=64 fp16 (128B rows, SW128), 3-stage cp.async ring,
// one __syncthreads per K-tile, 2 CTAs/SM. 8 warps of 32x64.
// blockIdx.z = split-K slice (T tiles each). EPI: 0=none, 1=softplus.
#define STAGES 3
#define STG    32768u
#define GSMEM_TOTAL (STAGES * 32768)

template<int EPI>
__global__ __launch_bounds__(256, 2)
void gemm_mma(const __half* __restrict__ Ap, int lda,
              const __half* __restrict__ Bp, int ldb,
              float* __restrict__ C, int ldc, int T, long csplit)
{
    extern __shared__ __align__(1024) char smem[];
    const unsigned sb = smem_u32(smem);
    const int tid  = threadIdx.x;
    const int lane = tid & 31;
    const int wid  = tid >> 5;
    const int wm   = (wid & 3) * 32;   // warp row offset
    const int wn   = (wid >> 2) * 64;  // warp col offset
    const long bm  = (long)blockIdx.y * 128;
    const long bn  = (long)blockIdx.x * 128;

    Ap += (long)blockIdx.z * T * 64;
    Bp += (long)blockIdx.z * T * 64;
    C  += (long)blockIdx.z * csplit;

    const int ldr  = tid >> 3;
    const int ldc8 = (tid & 7) * 8;

    float acc[2][8][4];
#pragma unroll
    for (int i = 0; i < 2; i++)
#pragma unroll
        for (int j = 0; j < 8; j++)
#pragma unroll
            for (int r = 0; r < 4; r++) acc[i][j][r] = 0.0f;

    auto load_tile = [&](int t, int s) {
        const __half* Ab = Ap + bm * lda + (long)t * 64;
        const __half* Bb = Bp + bn * ldb + (long)t * 64;
        unsigned oa = sb + (unsigned)s * STG;
        unsigned ob = oa + 16384u;
#pragma unroll
        for (int i = 0; i < 4; i++) {
            int r = ldr + 32 * i;
            unsigned sw = SWZ128((unsigned)(r * 128 + ldc8 * 2));
            CP_ASYNC16(oa + sw, Ab + (long)r * lda + ldc8);
            CP_ASYNC16(ob + sw, Bb + (long)r * ldb + ldc8);
        }
        CP_COMMIT();
    };

#pragma unroll
    for (int s = 0; s < STAGES - 1; s++) {
        if (s < T) load_tile(s, s);
        else       CP_COMMIT();
    }

    const int lr = lane & 15;
    const int lh = (lane >> 4) * 16;

    int stage = 0;
    for (int t = 0; t < T; t++) {
        CP_WAIT(STAGES - 2);
        __syncthreads();
        {
            int tn = t + STAGES - 1;
            int sn = stage + STAGES - 1; if (sn >= STAGES) sn -= STAGES;
            if (tn < T) load_tile(tn, sn);
            else        CP_COMMIT();
        }
        const unsigned sA = sb + (unsigned)stage * STG;
        const unsigned sB = sA + 16384u;
#pragma unroll
        for (int ks = 0; ks < 4; ks++) {
            const int kb = ks * 32;
            unsigned af[2][4];
#pragma unroll
            for (int im = 0; im < 2; im++) {
                unsigned addr = sA + SWZ128((unsigned)((wm + im * 16 + lr) * 128 + kb + lh));
                ldsm4(af[im], addr);
            }
            unsigned bf[8][2];
#pragma unroll
            for (int jn = 0; jn < 4; jn++) {
                unsigned q[4];
                unsigned addr = sB + SWZ128((unsigned)((wn + jn * 16 + lr) * 128 + kb + lh));
                ldsm4(q, addr);
                bf[2 * jn][0]     = q[0];
                bf[2 * jn][1]     = q[2];
                bf[2 * jn + 1][0] = q[1];
                bf[2 * jn + 1][1] = q[3];
            }
#pragma unroll
            for (int im = 0; im < 2; im++)
#pragma unroll
                for (int j = 0; j < 8; j++)
                    mma16816(acc[im][j], af[im], bf[j]);
        }
        if (++stage == STAGES) stage = 0;
    }

    const int gid = lane >> 2;
    const int tig = lane & 3;
#pragma unroll
    for (int im = 0; im < 2; im++) {
        long m0 = bm + wm + im * 16 + gid;
#pragma unroll
        for (int j = 0; j < 8; j++) {
            long n0 = bn + wn + j * 8 + 2 * tig;
            float c0 = acc[im][j][0], c1 = acc[im][j][1];
            float c2 = acc[im][j][2], c3 = acc[im][j][3];
            if (EPI == 1) {
                c0 = softplusf(c0); c1 = softplusf(c1);
                c2 = softplusf(c2); c3 = softplusf(c3);
            }
            *reinterpret_cast<float2*>(C + m0 * ldc + n0)       = make_float2(c0, c1);
            *reinterpret_cast<float2*>(C + (m0 + 8) * ldc + n0) = make_float2(c2, c3);
        }
    }
}

// ---------------- depthwise causal conv(4) + bias + SiLU + u-fp16 ----------
__global__ __launch_bounds__(256)
void conv_silu_kernel(const float* __restrict__ Wconv,
                      const float* __restrict__ bconv)
{
    long idx = (long)blockIdx.x * 256 + threadIdx.x;   // over B * L/4 * D
    int d  = (int)(idx & (D_INNER - 1));
    int t4 = (int)((idx >> 12) & (L_SEQ / 4 - 1));
    int b  = (int)(idx >> 20);
    int t0 = t4 * 4;

    float w0 = Wconv[d * 4 + 0], w1 = Wconv[d * 4 + 1];
    float w2 = Wconv[d * 4 + 2], w3 = Wconv[d * 4 + 3];
    float bc = bconv[d];

    const long rowbase = (long)(b * L_SEQ) * (2 * D_INNER) + d;
    float v[7];
#pragma unroll
    for (int i = 0; i < 7; i++) {
        int tt = t0 - 3 + i;
        v[i] = (tt >= 0) ? g_xz[rowbase + (long)tt * (2 * D_INNER)] : 0.0f;
    }

    long m = (long)(b * L_SEQ + t0);
#pragma unroll
    for (int q = 0; q < 4; q++) {
        float acc = bc;
        acc = fmaf(v[q],     w0, acc);
        acc = fmaf(v[q + 1], w1, acc);
        acc = fmaf(v[q + 2], w2, acc);
        acc = fmaf(v[q + 3], w3, acc);
        float uu = siluf(acc);
        g_u[(m + q) * D_INNER + d] = uu;
        g_ap[(m + q) * D_INNER + d] = __float2half_rn(uu);
    }
}

// ---------------- selective scan + epilogue + y-fp16 -----------------------
// (inner loop frozen at R14 form — measured optimum)
__global__ __launch_bounds__(128)
void scan_kernel(const float* __restrict__ A_log,
                 const float* __restrict__ Dp)
{
    extern __shared__ __align__(16) float sBC[];   // [L_SEQ][32]
    const int b = blockIdx.x >> 5;
    const int d = ((blockIdx.x & 31) << 7) + threadIdx.x;
    const long base = (long)b * L_SEQ;

    for (int i = threadIdx.x * 4; i < L_SEQ * 32; i += 128 * 4) {
        int t = i >> 5, c = i & 31;
        *reinterpret_cast<float4*>(&sBC[i]) =
            *reinterpret_cast<const float4*>(&g_xdbl[(base + t) * XDBL_LD + DT_RANK + c]);
    }
    __syncthreads();

    float A[N_STATE];
#pragma unroll
    for (int n = 0; n < N_STATE; n++)
        A[n] = -__expf(A_log[d * N_STATE + n]);
    const float A1 = A[0];
    bool fast = true;
#pragma unroll
    for (int n = 1; n < N_STATE; n++)
        fast = fast && (fabsf(A[n] - (float)(n + 1) * A1) <= 1e-4f * fabsf(A[n]) + 1e-30f);

    const float Dd = Dp[d];
    float h[N_STATE];
#pragma unroll
    for (int n = 0; n < N_STATE; n++) h[n] = 0.0f;

    float pdt[4], pu[4], pr[4];
#pragma unroll
    for (int q = 0; q < 4; q++) {
        long row = base + q;
        pdt[q] = g_delta[row * D_INNER + d];
        pu[q]  = g_u[row * D_INNER + d];
        pr[q]  = g_xz[row * (2 * D_INNER) + D_INNER + d];
    }

    for (int t0 = 0; t0 < L_SEQ; t0 += 4) {
        float cdt[4], cu[4], cr[4];
#pragma unroll
        for (int q = 0; q < 4; q++) { cdt[q] = pdt[q]; cu[q] = pu[q]; cr[q] = pr[q]; }
        if (t0 + 4 < L_SEQ) {
#pragma unroll
            for (int q = 0; q < 4; q++) {
                long row = base + t0 + 4 + q;
                pdt[q] = g_delta[row * D_INNER + d];
                pu[q]  = g_u[row * D_INNER + d];
                pr[q]  = g_xz[row * (2 * D_INNER) + D_INNER + d];
            }
        }
#pragma unroll
        for (int q = 0; q < 4; q++) {
            const int t = t0 + q;
            const float* BC = &sBC[t * 32];
            const float dt = cdt[q], uu = cu[q], rr = cr[q];
            const float dtu = dt * uu;
            float yv = 0.0f;
            if (fast) {
                const float p = __expf(dt * A1);
                float da = p;
#pragma unroll
                for (int n = 0; n < N_STATE; n++) {
                    h[n] = fmaf(da, h[n], dtu * BC[n]);
                    yv = fmaf(h[n], BC[N_STATE + n], yv);
                    da *= p;
                }
            } else {
#pragma unroll
                for (int n = 0; n < N_STATE; n++) {
                    float da = __expf(dt * A[n]);
                    h[n] = fmaf(da, h[n], dtu * BC[n]);
                    yv = fmaf(h[n], BC[N_STATE + n], yv);
                }
            }
            float yo = (yv + uu * Dd) * siluf(rr);
            g_ap[(base + t) * D_INNER + d] = __float2half_rn(yo);
        }
    }
}

// ---------------- launcher ----------------
extern "C" void kernel_launch(void* const* d_in, const int* in_sizes, int n_in,
                              void* d_out, int out_size)
{
    (void)in_sizes; (void)n_in; (void)out_size;
    const float* x     = (const float*)d_in[0];
    const float* Win   = (const float*)d_in[1];
    const float* Wconv = (const float*)d_in[2];
    const float* bconv = (const float*)d_in[3];
    const float* Wx    = (const float*)d_in[4];
    const float* Wdt   = (const float*)d_in[5];
    const float* A_log = (const float*)d_in[6];
    const float* D     = (const float*)d_in[7];
    const float* Wout  = (const float*)d_in[8];
    float* out = (float*)d_out;

    float *xz, *xdbl, *delta, *partx, *party;
    __half *ap, *ax, *ap2, *wpA, *wpB, *wpC, *wpD;
    cudaGetSymbolAddress((void**)&xz,    g_xz);
    cudaGetSymbolAddress((void**)&xdbl,  g_xdbl);
    cudaGetSymbolAddress((void**)&delta, g_delta);
    cudaGetSymbolAddress((void**)&partx, g_partx);
    cudaGetSymbolAddress((void**)&party, g_party);
    cudaGetSymbolAddress((void**)&ap,    g_ap);
    cudaGetSymbolAddress((void**)&ax,    g_ax);
    cudaGetSymbolAddress((void**)&ap2,   g_ap2);
    cudaGetSymbolAddress((void**)&wpA,   g_wpA);
    cudaGetSymbolAddress((void**)&wpB,   g_wpB);
    cudaGetSymbolAddress((void**)&wpC,   g_wpC);
    cudaGetSymbolAddress((void**)&wpD,   g_wpD);

    cudaFuncSetAttribute(gemm_mma<0>, cudaFuncAttributeMaxDynamicSharedMemorySize, GSMEM_TOTAL);
    cudaFuncSetAttribute(gemm_mma<1>, cudaFuncAttributeMaxDynamicSharedMemorySize, GSMEM_TOTAL);
    const int scan_smem = L_SEQ * 32 * sizeof(float);
    cudaFuncSetAttribute(scan_kernel, cudaFuncAttributeMaxDynamicSharedMemorySize, scan_smem);

    // ---- ONE fused prep: all weight transposes + x quantize ----
    prep_all<<<PREP_BLOCKS, 256>>>(x, Win, Wx, Wdt, Wout);

    // ---- GEMM1: xz = x @ Win   (2048 x 8192, K=1024, T=16) ----
    gemm_mma<0><<<dim3(2 * D_INNER / 128, M_ROWS / 128, 1), 256, GSMEM_TOTAL>>>(
        ax, D_MODEL, wpA, D_MODEL, xz, 2 * D_INNER, 16, 0);

    // ---- conv + SiLU -> u (fp32) + u (fp16, into ap) ----
    conv_silu_kernel<<<(B_SZ * (L_SEQ / 4) * D_INNER) / 256, 256>>>(Wconv, bconv);

    // ---- x_dbl = u @ Wx   (2048 x 128pad, K=4096; split-K x8, T=8) ----
    gemm_mma<0><<<dim3(1, M_ROWS / 128, 8), 256, GSMEM_TOTAL>>>(
        ap, D_INNER, wpB, D_INNER, partx, XDBL_LD, 8, (long)M_ROWS * XDBL_LD);
    // fused: reduce + fp16 emit of delta-GEMM input (cols 0..63)
    reduce_xdbl<<<(M_ROWS * XDBL_LD) / 1024, 256>>>(partx, xdbl, ap2,
                                                    (long)M_ROWS * XDBL_LD, 8);

    // ---- delta = softplus(x_dbl[:, :64] @ Wdt)  (2048 x 4096, K=64, T=1) ----
    gemm_mma<1><<<dim3(D_INNER / 128, M_ROWS / 128, 1), 256, GSMEM_TOTAL>>>(
        ap2, DT_RANK, wpC, DT_RANK, delta, D_INNER, 1, 0);

    // ---- selective scan + epilogue -> y (fp16, into ap) ----
    scan_kernel<<<64, 128, scan_smem>>>(A_log, D);

    // ---- out = y @ Wout   (2048 x 1024, K=4096; split-K x4, T=16) ----
    gemm_mma<0><<<dim3(D_MODEL / 128, M_ROWS / 128, 4), 256, GSMEM_TOTAL>>>(
        ap, D_INNER, wpD, D_INNER, party, D_MODEL, 16, (long)M_ROWS * D_MODEL);
    reduce_parts<<<(M_ROWS * D_MODEL) / 1024, 256>>>(party, out, (long)M_ROWS * D_MODEL, 4);
}